// round 2
// baseline (speedup 1.0000x reference)
#include <cuda_runtime.h>
#include <cstdint>
#include <cstddef>

#define DEV __device__ __forceinline__

// ---------------- problem dims ----------------
constexpr int BATCH = 8192;
constexpr int FEAT  = 4096;

// ---------------- tiling ----------------
constexpr int BM = 256;
constexpr int BN = 128;
constexpr int BK = 32;                    // tf32 floats per k-tile (128 B rows)
constexpr int NKT = FEAT / BK;            // 128
constexpr int NSTAGE = 4;

constexpr int A_TILE_BYTES = BM * BK * 4; // 32768
constexpr int B_TILE_BYTES = BN * BK * 4; // 16384
constexpr int OFF_B = A_TILE_BYTES;
constexpr int STAGE_BYTES = A_TILE_BYTES + B_TILE_BYTES;       // 49152

constexpr int SM_MBAR = 0;                // 4 mbarriers
constexpr int SM_DATA = 1024;
constexpr int SMEM_TOTAL = SM_DATA + NSTAGE * STAGE_BYTES;     // 197632

constexpr int MT = BATCH / BM;            // 32
constexpr int NT = FEAT / BN;             // 32

// ---------------- device scratch (tile-major, pre-swizzled) ----------------
// g_X: [mt(32)][kt(128)] tiles of 256x32 floats (32KB each), SW-swizzled
// g_W: [nt(32)][kt(128)] tiles of 128x32 floats (16KB each), SW-swizzled
__device__ float g_X[(size_t)BATCH * FEAT];
__device__ float g_W[(size_t)FEAT * FEAT];

// ---------------- helpers ----------------
DEV uint32_t smem_u32(const void* p) {
    uint32_t a;
    asm("{ .reg .u64 t; cvta.to.shared.u64 t, %1; cvt.u32.u64 %0, t; }" : "=r"(a) : "l"(p));
    return a;
}
DEV float rna_tf32(float f) {
    uint32_t u;
    asm("cvt.rna.tf32.f32 %0, %1;" : "=r"(u) : "f"(f));
    return __uint_as_float(u);
}

DEV void mbar_init(uint32_t a, uint32_t cnt) {
    asm volatile("mbarrier.init.shared.b64 [%0], %1;" :: "r"(a), "r"(cnt) : "memory");
}
DEV void mbar_expect_tx(uint32_t a, uint32_t bytes) {
    asm volatile("mbarrier.arrive.expect_tx.shared.b64 _, [%0], %1;"
                 :: "r"(a), "r"(bytes) : "memory");
}
DEV void mbar_wait(uint32_t a, uint32_t parity) {
    asm volatile(
        "{\n\t.reg .pred P;\n\t"
        "WL%=:\n\t"
        "mbarrier.try_wait.parity.acquire.cta.shared::cta.b64 P, [%0], %1, 0x989680;\n\t"
        "@P bra.uni WD%=;\n\t"
        "bra.uni WL%=;\n\t"
        "WD%=:\n\t}"
        :: "r"(a), "r"(parity) : "memory");
}
DEV void bulk_g2s(uint32_t dst, const void* src, uint32_t bytes, uint32_t mbar) {
    asm volatile(
        "cp.async.bulk.shared::cluster.global.mbarrier::complete_tx::bytes [%0], [%1], %2, [%3];"
        :: "r"(dst), "l"(src), "r"(bytes), "r"(mbar) : "memory");
}

DEV void ldsm4(uint32_t& r0, uint32_t& r1, uint32_t& r2, uint32_t& r3, uint32_t addr) {
    asm volatile("ldmatrix.sync.aligned.m8n8.x4.shared.b16 {%0,%1,%2,%3}, [%4];"
                 : "=r"(r0), "=r"(r1), "=r"(r2), "=r"(r3) : "r"(addr));
}
DEV void mma_tf32(float* d, const uint32_t* a, const uint32_t* b) {
    asm volatile(
        "mma.sync.aligned.m16n8k8.row.col.f32.tf32.tf32.f32 "
        "{%0,%1,%2,%3}, {%4,%5,%6,%7}, {%8,%9}, {%0,%1,%2,%3};"
        : "+f"(d[0]), "+f"(d[1]), "+f"(d[2]), "+f"(d[3])
        : "r"(a[0]), "r"(a[1]), "r"(a[2]), "r"(a[3]), "r"(b[0]), "r"(b[1]));
}

// ---------------- prep: tf32-round + pack into swizzled tile-major ----------------
// X: tile (32KB) = 2048 x 16B chunks; chunk (row, c): row 0..255, c 0..7
// phys chunk index = row*8 + (c ^ (row & 7))   -> conflict-free ldmatrix later
__global__ void k_pack_x(const float* __restrict__ x) {
    size_t gci = (size_t)blockIdx.x * 256 + threadIdx.x;     // 8M chunks
    int tile = (int)(gci >> 11);
    int ci   = (int)(gci & 2047);
    int bm = tile >> 7, kt = tile & 127;
    int row = ci >> 3, c = ci & 7;
    size_t src4 = (size_t)(bm * 256 + row) * (FEAT / 4) + kt * 8 + c;
    float4 v = reinterpret_cast<const float4*>(x)[src4];
    v.x = rna_tf32(v.x); v.y = rna_tf32(v.y); v.z = rna_tf32(v.z); v.w = rna_tf32(v.w);
    size_t dst4 = ((size_t)tile << 11) + (row << 3) + (c ^ (row & 7));
    reinterpret_cast<float4*>(g_X)[dst4] = v;
}

// W_big[o][i] = sign * W_{src}[o%1024][i%1024] per Hamilton block table; out = x @ W_big^T
__global__ void k_pack_w(const float* __restrict__ wrr, const float* __restrict__ wri,
                         const float* __restrict__ wrj, const float* __restrict__ wrk) {
    size_t gci = (size_t)blockIdx.x * 256 + threadIdx.x;     // 4M chunks
    int tile = (int)(gci >> 10);
    int ci   = (int)(gci & 1023);
    int bn = tile >> 7, kt = tile & 127;
    int row = ci >> 3, c = ci & 7;
    int o = bn * 128 + row;
    int k = kt * 32 + c * 4;
    int qo = o >> 10, qi = k >> 10;
    const int   st[16] = {0,1,2,3,  1,0,3,2,  2,3,0,1,  3,2,1,0};
    const float gt[16] = {1,-1,-1,-1,  1,1,1,-1,  1,-1,1,1,  1,1,-1,1};
    const float* srcs[4] = {wrr, wri, wrj, wrk};
    int   si = st[qo * 4 + qi];
    float sg = gt[qo * 4 + qi];
    const float* src = srcs[si] + (size_t)(o & 1023) * 1024 + (k & 1023);
    float4 v = *reinterpret_cast<const float4*>(src);
    v.x = rna_tf32(sg * v.x); v.y = rna_tf32(sg * v.y);
    v.z = rna_tf32(sg * v.z); v.w = rna_tf32(sg * v.w);
    size_t dst4 = ((size_t)tile << 10) + (row << 3) + (c ^ (row & 7));
    reinterpret_cast<float4*>(g_W)[dst4] = v;
}

// ---------------- main GEMM: 512 threads, warp grid 4(M) x 4(N), warp tile 64x32 ----
__global__ void __launch_bounds__(512, 1)
k_qdense(const float* __restrict__ brr, float* __restrict__ out) {
    extern __shared__ char smem[];
    uint32_t sb = smem_u32(smem);
    int tid = threadIdx.x, wid = tid >> 5, lane = tid & 31;
    int wm = wid >> 2, wn = wid & 3;

    int mt = blockIdx.x >> 5;
    int nt = blockIdx.x & 31;          // n-fast: 32 consecutive CTAs share one A m-tile

    if (tid == 0) {
#pragma unroll
        for (int s = 0; s < NSTAGE; s++) mbar_init(sb + SM_MBAR + 8 * s, 1);
    }
    __syncthreads();

    const float* srcA = g_X + ((size_t)mt * NKT) * (BM * BK);
    const float* srcB = g_W + ((size_t)nt * NKT) * (BN * BK);

    auto issue = [&](int kt, int s) {
        uint32_t mb = sb + SM_MBAR + 8 * s;
        uint32_t st = sb + SM_DATA + s * STAGE_BYTES;
        mbar_expect_tx(mb, STAGE_BYTES);
        bulk_g2s(st,         srcA + (size_t)kt * (BM * BK), A_TILE_BYTES, mb);
        bulk_g2s(st + OFF_B, srcB + (size_t)kt * (BN * BK), B_TILE_BYTES, mb);
    };

    if (tid == 0) {
#pragma unroll
        for (int p = 0; p < NSTAGE - 1; p++) issue(p, p);
    }

    float acc[4][4][4];
#pragma unroll
    for (int i = 0; i < 4; i++)
#pragma unroll
        for (int j = 0; j < 4; j++)
#pragma unroll
            for (int v = 0; v < 4; v++) acc[i][j][v] = 0.0f;

    // per-lane ldmatrix addressing components
    int a_rowl_base = ((lane >> 3) & 1) * 8 + (lane & 7);   // + mf*16
    int a_chunk_sel = lane >> 4;                            // + ks*2
    int b_rowl_base = ((lane >> 4) << 3) + (lane & 7);      // + nf2*16
    int b_chunk_sel = (lane >> 3) & 1;                      // + ks*2

#pragma unroll 1
    for (int kt = 0; kt < NKT; kt++) {
        int s = kt & 3;
        __syncthreads();                                    // everyone done with stage (kt-1)&3
        if (tid == 0 && kt + (NSTAGE - 1) < NKT)
            issue(kt + NSTAGE - 1, (kt + NSTAGE - 1) & 3);  // refill the stage just freed
        mbar_wait(sb + SM_MBAR + 8 * s, (kt >> 2) & 1);

        uint32_t abase = sb + SM_DATA + s * STAGE_BYTES + wm * (64 * 128);
        uint32_t bbase = sb + SM_DATA + s * STAGE_BYTES + OFF_B + wn * (32 * 128);

#pragma unroll
        for (int ks = 0; ks < 4; ks++) {
            uint32_t a[4][4];
#pragma unroll
            for (int mf = 0; mf < 4; mf++) {
                int rowl = mf * 16 + a_rowl_base;
                int chunk = ks * 2 + a_chunk_sel;
                uint32_t addr = abase + rowl * 128 + ((chunk ^ (rowl & 7)) << 4);
                ldsm4(a[mf][0], a[mf][1], a[mf][2], a[mf][3], addr);
            }
            uint32_t b[4][2];
#pragma unroll
            for (int nf2 = 0; nf2 < 2; nf2++) {
                int rowl = nf2 * 16 + b_rowl_base;
                int chunk = ks * 2 + b_chunk_sel;
                uint32_t addr = bbase + rowl * 128 + ((chunk ^ (rowl & 7)) << 4);
                ldsm4(b[2 * nf2][0], b[2 * nf2][1], b[2 * nf2 + 1][0], b[2 * nf2 + 1][1], addr);
            }
#pragma unroll
            for (int mf = 0; mf < 4; mf++)
#pragma unroll
                for (int nf = 0; nf < 4; nf++)
                    mma_tf32(acc[mf][nf], a[mf], b[nf]);
        }
    }

    // ---------------- epilogue: acc + bias -> out ----------------
#pragma unroll
    for (int nf = 0; nf < 4; nf++) {
        int col = nt * BN + wn * 32 + nf * 8 + (lane & 3) * 2;
        int bidx = col & 1023;
        float bi0 = __ldg(brr + bidx);
        float bi1 = __ldg(brr + bidx + 1);
#pragma unroll
        for (int mf = 0; mf < 4; mf++) {
            size_t row0 = (size_t)mt * BM + wm * 64 + mf * 16 + (lane >> 2);
            float2 v0 = make_float2(acc[mf][nf][0] + bi0, acc[mf][nf][1] + bi1);
            float2 v1 = make_float2(acc[mf][nf][2] + bi0, acc[mf][nf][3] + bi1);
            *reinterpret_cast<float2*>(out + row0 * FEAT + col) = v0;
            *reinterpret_cast<float2*>(out + (row0 + 8) * FEAT + col) = v1;
        }
    }
}

// ---------------- launch ----------------
extern "C" void kernel_launch(void* const* d_in, const int* in_sizes, int n_in,
                              void* d_out, int out_size) {
    const float* x   = (const float*)d_in[0];
    const float* wrr = (const float*)d_in[1];
    const float* wri = (const float*)d_in[2];
    const float* wrj = (const float*)d_in[3];
    const float* wrk = (const float*)d_in[4];
    const float* brr = (const float*)d_in[5];
    float* out = (float*)d_out;

    // pack + tf32-round operands into tile-major swizzled scratch
    k_pack_x<<<(int)(((size_t)BATCH * FEAT / 4) / 256), 256>>>(x);
    k_pack_w<<<(int)(((size_t)FEAT * FEAT / 4) / 256), 256>>>(wrr, wri, wrj, wrk);

    static int smem_set = 0;
    if (!smem_set) {
        cudaFuncSetAttribute(k_qdense, cudaFuncAttributeMaxDynamicSharedMemorySize, SMEM_TOTAL);
        smem_set = 1;
    }
    k_qdense<<<MT * NT, 512, SMEM_TOTAL>>>(brr, out);
}

// round 3
// speedup vs baseline: 1.9159x; 1.9159x over previous
#include <cuda_runtime.h>
#include <cuda_fp16.h>
#include <cstdint>
#include <cstddef>

#define DEV __device__ __forceinline__

// ---------------- problem dims ----------------
constexpr int BATCH = 8192;
constexpr int FEAT  = 4096;

// ---------------- tiling ----------------
constexpr int BM = 256;
constexpr int BN = 128;
constexpr int BK = 64;                    // fp16 elems per k-tile (128 B rows)
constexpr int NKT = FEAT / BK;            // 64
constexpr int NSTAGE = 4;

constexpr int A_TILE_BYTES = BM * BK * 2; // 32768
constexpr int B_TILE_BYTES = BN * BK * 2; // 16384
constexpr int OFF_B = A_TILE_BYTES;
constexpr int STAGE_BYTES = A_TILE_BYTES + B_TILE_BYTES;       // 49152

constexpr int SM_MBAR = 0;                // 4 mbarriers
constexpr int SM_DATA = 1024;
constexpr int SMEM_TOTAL = SM_DATA + NSTAGE * STAGE_BYTES;     // 197632

constexpr int MT = BATCH / BM;            // 32
constexpr int NT = FEAT / BN;             // 32

// ---------------- device scratch (tile-major, pre-swizzled fp16) ----------------
// g_X: [mt(32)][kt(64)] tiles of 256x64 halves (32KB each), XOR-swizzled 16B chunks
// g_W: [nt(32)][kt(64)] tiles of 128x64 halves (16KB each), XOR-swizzled
__device__ __half g_X[(size_t)BATCH * FEAT];
__device__ __half g_W[(size_t)FEAT * FEAT];

// ---------------- helpers ----------------
DEV uint32_t smem_u32(const void* p) {
    uint32_t a;
    asm("{ .reg .u64 t; cvta.to.shared.u64 t, %1; cvt.u32.u64 %0, t; }" : "=r"(a) : "l"(p));
    return a;
}

DEV void mbar_init(uint32_t a, uint32_t cnt) {
    asm volatile("mbarrier.init.shared.b64 [%0], %1;" :: "r"(a), "r"(cnt) : "memory");
}
DEV void mbar_expect_tx(uint32_t a, uint32_t bytes) {
    asm volatile("mbarrier.arrive.expect_tx.shared.b64 _, [%0], %1;"
                 :: "r"(a), "r"(bytes) : "memory");
}
DEV void mbar_wait(uint32_t a, uint32_t parity) {
    asm volatile(
        "{\n\t.reg .pred P;\n\t"
        "WL%=:\n\t"
        "mbarrier.try_wait.parity.acquire.cta.shared::cta.b64 P, [%0], %1, 0x989680;\n\t"
        "@P bra.uni WD%=;\n\t"
        "bra.uni WL%=;\n\t"
        "WD%=:\n\t}"
        :: "r"(a), "r"(parity) : "memory");
}
DEV void bulk_g2s(uint32_t dst, const void* src, uint32_t bytes, uint32_t mbar) {
    asm volatile(
        "cp.async.bulk.shared::cluster.global.mbarrier::complete_tx::bytes [%0], [%1], %2, [%3];"
        :: "r"(dst), "l"(src), "r"(bytes), "r"(mbar) : "memory");
}

DEV void ldsm4(uint32_t& r0, uint32_t& r1, uint32_t& r2, uint32_t& r3, uint32_t addr) {
    asm volatile("ldmatrix.sync.aligned.m8n8.x4.shared.b16 {%0,%1,%2,%3}, [%4];"
                 : "=r"(r0), "=r"(r1), "=r"(r2), "=r"(r3) : "r"(addr));
}
DEV void mma_f16(float* d, const uint32_t* a, const uint32_t* b) {
    asm volatile(
        "mma.sync.aligned.m16n8k16.row.col.f32.f16.f16.f32 "
        "{%0,%1,%2,%3}, {%4,%5,%6,%7}, {%8,%9}, {%0,%1,%2,%3};"
        : "+f"(d[0]), "+f"(d[1]), "+f"(d[2]), "+f"(d[3])
        : "r"(a[0]), "r"(a[1]), "r"(a[2]), "r"(a[3]), "r"(b[0]), "r"(b[1]));
}

DEV uint32_t pack2(float lo, float hi) {
    __half2 h = __halves2half2(__float2half_rn(lo), __float2half_rn(hi));
    return *reinterpret_cast<uint32_t*>(&h);
}

// ---------------- prep: fp16-round + pack into swizzled tile-major ----------------
// Each thread produces one 16B dst chunk (8 fp16) from 32B of f32 source.
// phys chunk index in tile = row*8 + (c ^ (row & 7))
__global__ void k_pack_x(const float* __restrict__ x) {
    size_t gci = (size_t)blockIdx.x * 256 + threadIdx.x;     // 4M chunks
    int tile = (int)(gci >> 11);          // 2048 chunks per 256x64 tile
    int ci   = (int)(gci & 2047);
    int bm = tile >> 6, kt = tile & 63;
    int row = ci >> 3, c = ci & 7;
    const float4* src = reinterpret_cast<const float4*>(
        x + (size_t)(bm * 256 + row) * FEAT + kt * 64 + c * 8);
    float4 v0 = src[0], v1 = src[1];
    uint4 d;
    d.x = pack2(v0.x, v0.y); d.y = pack2(v0.z, v0.w);
    d.z = pack2(v1.x, v1.y); d.w = pack2(v1.z, v1.w);
    size_t dst = ((size_t)tile << 11) + (row << 3) + (c ^ (row & 7));
    reinterpret_cast<uint4*>(g_X)[dst] = d;
}

// W_big[o][i] = sign * W_{src}[o%1024][i%1024] per Hamilton block table; out = x @ W_big^T
__global__ void k_pack_w(const float* __restrict__ wrr, const float* __restrict__ wri,
                         const float* __restrict__ wrj, const float* __restrict__ wrk) {
    size_t gci = (size_t)blockIdx.x * 256 + threadIdx.x;     // 2M chunks
    int tile = (int)(gci >> 10);          // 1024 chunks per 128x64 tile
    int ci   = (int)(gci & 1023);
    int bn = tile >> 6, kt = tile & 63;
    int row = ci >> 3, c = ci & 7;
    int o = bn * 128 + row;
    int k = kt * 64 + c * 8;
    int qo = o >> 10, qi = k >> 10;
    const int   st[16] = {0,1,2,3,  1,0,3,2,  2,3,0,1,  3,2,1,0};
    const float gt[16] = {1,-1,-1,-1,  1,1,1,-1,  1,-1,1,1,  1,1,-1,1};
    const float* srcs[4] = {wrr, wri, wrj, wrk};
    int   si = st[qo * 4 + qi];
    float sg = gt[qo * 4 + qi];
    const float4* src = reinterpret_cast<const float4*>(
        srcs[si] + (size_t)(o & 1023) * 1024 + (k & 1023));
    float4 v0 = src[0], v1 = src[1];
    uint4 d;
    d.x = pack2(sg * v0.x, sg * v0.y); d.y = pack2(sg * v0.z, sg * v0.w);
    d.z = pack2(sg * v1.x, sg * v1.y); d.w = pack2(sg * v1.z, sg * v1.w);
    size_t dst = ((size_t)tile << 10) + (row << 3) + (c ^ (row & 7));
    reinterpret_cast<uint4*>(g_W)[dst] = d;
}

// ---------------- main GEMM: 512 threads, warp grid 4(M) x 4(N), warp tile 64x32 ----
__global__ void __launch_bounds__(512, 1)
k_qdense(const float* __restrict__ brr, float* __restrict__ out) {
    extern __shared__ char smem[];
    uint32_t sb = smem_u32(smem);
    int tid = threadIdx.x, wid = tid >> 5, lane = tid & 31;
    int wm = wid >> 2, wn = wid & 3;

    int mt = blockIdx.x >> 5;
    int nt = blockIdx.x & 31;          // n-fast: 32 consecutive CTAs share one A m-tile

    if (tid == 0) {
#pragma unroll
        for (int s = 0; s < NSTAGE; s++) mbar_init(sb + SM_MBAR + 8 * s, 1);
    }
    __syncthreads();

    const __half* srcA = g_X + ((size_t)mt * NKT) * (BM * BK);
    const __half* srcB = g_W + ((size_t)nt * NKT) * (BN * BK);

    auto issue = [&](int kt, int s) {
        uint32_t mb = sb + SM_MBAR + 8 * s;
        uint32_t st = sb + SM_DATA + s * STAGE_BYTES;
        mbar_expect_tx(mb, STAGE_BYTES);
        bulk_g2s(st,         srcA + (size_t)kt * (BM * BK), A_TILE_BYTES, mb);
        bulk_g2s(st + OFF_B, srcB + (size_t)kt * (BN * BK), B_TILE_BYTES, mb);
    };

    if (tid == 0) {
#pragma unroll
        for (int p = 0; p < NSTAGE - 1; p++) issue(p, p);
    }

    float acc[4][4][4];
#pragma unroll
    for (int i = 0; i < 4; i++)
#pragma unroll
        for (int j = 0; j < 4; j++)
#pragma unroll
            for (int v = 0; v < 4; v++) acc[i][j][v] = 0.0f;

    // per-lane ldmatrix addressing (rows are 128B = 8 chunks of 16B, XOR swizzle)
    int a_rowl_base = ((lane >> 3) & 1) * 8 + (lane & 7);   // + mf*16
    int a_chunk_sel = lane >> 4;                            // + ks*2
    int b_rowl_base = ((lane >> 4) << 3) + (lane & 7);      // + nf2*16
    int b_chunk_sel = (lane >> 3) & 1;                      // + ks*2

#pragma unroll 1
    for (int kt = 0; kt < NKT; kt++) {
        int s = kt & 3;
        __syncthreads();                                    // all warps done with stage s's old tile
        if (tid == 0 && kt + (NSTAGE - 1) < NKT)
            issue(kt + NSTAGE - 1, (kt + NSTAGE - 1) & 3);
        mbar_wait(sb + SM_MBAR + 8 * s, (kt >> 2) & 1);

        uint32_t abase = sb + SM_DATA + s * STAGE_BYTES + wm * (64 * 128);
        uint32_t bbase = sb + SM_DATA + s * STAGE_BYTES + OFF_B + wn * (32 * 128);

#pragma unroll
        for (int ks = 0; ks < 4; ks++) {                    // 4 x k16 per k-tile
            uint32_t a[4][4];
#pragma unroll
            for (int mf = 0; mf < 4; mf++) {
                int rowl = mf * 16 + a_rowl_base;
                int chunk = ks * 2 + a_chunk_sel;
                uint32_t addr = abase + rowl * 128 + ((chunk ^ (rowl & 7)) << 4);
                ldsm4(a[mf][0], a[mf][1], a[mf][2], a[mf][3], addr);
            }
            uint32_t b[4][2];
#pragma unroll
            for (int nf2 = 0; nf2 < 2; nf2++) {
                int rowl = nf2 * 16 + b_rowl_base;
                int chunk = ks * 2 + b_chunk_sel;
                uint32_t addr = bbase + rowl * 128 + ((chunk ^ (rowl & 7)) << 4);
                ldsm4(b[2 * nf2][0], b[2 * nf2][1], b[2 * nf2 + 1][0], b[2 * nf2 + 1][1], addr);
            }
#pragma unroll
            for (int mf = 0; mf < 4; mf++)
#pragma unroll
                for (int nf = 0; nf < 4; nf++)
                    mma_f16(acc[mf][nf], a[mf], b[nf]);
        }
    }

    // ---------------- epilogue: acc + bias -> out ----------------
#pragma unroll
    for (int nf = 0; nf < 4; nf++) {
        int col = nt * BN + wn * 32 + nf * 8 + (lane & 3) * 2;
        int bidx = col & 1023;
        float bi0 = __ldg(brr + bidx);
        float bi1 = __ldg(brr + bidx + 1);
#pragma unroll
        for (int mf = 0; mf < 4; mf++) {
            size_t row0 = (size_t)mt * BM + wm * 64 + mf * 16 + (lane >> 2);
            float2 v0 = make_float2(acc[mf][nf][0] + bi0, acc[mf][nf][1] + bi1);
            float2 v1 = make_float2(acc[mf][nf][2] + bi0, acc[mf][nf][3] + bi1);
            *reinterpret_cast<float2*>(out + row0 * FEAT + col) = v0;
            *reinterpret_cast<float2*>(out + (row0 + 8) * FEAT + col) = v1;
        }
    }
}

// ---------------- launch ----------------
extern "C" void kernel_launch(void* const* d_in, const int* in_sizes, int n_in,
                              void* d_out, int out_size) {
    const float* x   = (const float*)d_in[0];
    const float* wrr = (const float*)d_in[1];
    const float* wri = (const float*)d_in[2];
    const float* wrj = (const float*)d_in[3];
    const float* wrk = (const float*)d_in[4];
    const float* brr = (const float*)d_in[5];
    float* out = (float*)d_out;

    // pack + fp16-round operands into tile-major swizzled scratch
    k_pack_x<<<(int)(((size_t)BATCH * FEAT / 8) / 256), 256>>>(x);
    k_pack_w<<<(int)(((size_t)FEAT * FEAT / 8) / 256), 256>>>(wrr, wri, wrj, wrk);

    static int smem_set = 0;
    if (!smem_set) {
        cudaFuncSetAttribute(k_qdense, cudaFuncAttributeMaxDynamicSharedMemorySize, SMEM_TOTAL);
        smem_set = 1;
    }
    k_qdense<<<MT * NT, 512, SMEM_TOTAL>>>(brr, out);
}

// round 4
// speedup vs baseline: 2.2042x; 1.1505x over previous
#include <cuda_runtime.h>
#include <cuda_fp16.h>
#include <cstdint>
#include <cstddef>

#define DEV __device__ __forceinline__

// ---------------- problem dims ----------------
constexpr int BATCH = 8192;
constexpr int FEAT  = 4096;
constexpr int Q     = 1024;

// ---------------- tiling ----------------
constexpr int BM = 128;                   // CTA rows
constexpr int BN = 128;                   // CTA cols (per output tile; CTA makes 2 tiles)
constexpr int BK = 64;                    // fp16 per k-tile (128B rows)
constexpr int KT_PER_PHASE = Q / BK;      // 16
constexpr int NPHASE = 6;
constexpr int TOTAL_IT = NPHASE * KT_PER_PHASE;  // 96
constexpr int NSTAGE = 5;

constexpr int A_TILE_BYTES = BM * BK * 2; // 16384
constexpr int B_TILE_BYTES = BN * BK * 2; // 16384
constexpr int OFF_B = A_TILE_BYTES;
constexpr int STAGE_BYTES = A_TILE_BYTES + B_TILE_BYTES;       // 32768

constexpr int SM_MBAR = 0;
constexpr int SM_DATA = 1024;
constexpr int SMEM_TOTAL = SM_DATA + NSTAGE * STAGE_BYTES;     // 164864

constexpr int MT = BATCH / BM;            // 64
constexpr int NT = Q / BN;                // 8

// tiles are 128x64 halves = 8192 halves = 1024 x 16B chunks
constexpr int TILE_HALVES = BM * BK;      // 8192

// ---------------- device scratch ----------------
// g_X: 6 A-matrices (x0,x1,x2,x3,x0+x1,x2+x3), each [mt(64)][kt(16)] tiles, swizzled
// g_W: 12 B-matrices (per-phase W combos, signs folded), each [nt(8)][kt(16)] tiles
__device__ __half g_X[(size_t)6 * BATCH * Q];
__device__ __half g_W[(size_t)12 * Q * Q];

// ---------------- helpers ----------------
DEV uint32_t smem_u32(const void* p) {
    uint32_t a;
    asm("{ .reg .u64 t; cvta.to.shared.u64 t, %1; cvt.u32.u64 %0, t; }" : "=r"(a) : "l"(p));
    return a;
}
DEV void mbar_init(uint32_t a, uint32_t cnt) {
    asm volatile("mbarrier.init.shared.b64 [%0], %1;" :: "r"(a), "r"(cnt) : "memory");
}
DEV void mbar_expect_tx(uint32_t a, uint32_t bytes) {
    asm volatile("mbarrier.arrive.expect_tx.shared.b64 _, [%0], %1;"
                 :: "r"(a), "r"(bytes) : "memory");
}
DEV void mbar_wait(uint32_t a, uint32_t parity) {
    asm volatile(
        "{\n\t.reg .pred P;\n\t"
        "WL%=:\n\t"
        "mbarrier.try_wait.parity.acquire.cta.shared::cta.b64 P, [%0], %1, 0x989680;\n\t"
        "@P bra.uni WD%=;\n\t"
        "bra.uni WL%=;\n\t"
        "WD%=:\n\t}"
        :: "r"(a), "r"(parity) : "memory");
}
DEV void bulk_g2s(uint32_t dst, const void* src, uint32_t bytes, uint32_t mbar) {
    asm volatile(
        "cp.async.bulk.shared::cluster.global.mbarrier::complete_tx::bytes [%0], [%1], %2, [%3];"
        :: "r"(dst), "l"(src), "r"(bytes), "r"(mbar) : "memory");
}
DEV void ldsm4(uint32_t& r0, uint32_t& r1, uint32_t& r2, uint32_t& r3, uint32_t addr) {
    asm volatile("ldmatrix.sync.aligned.m8n8.x4.shared.b16 {%0,%1,%2,%3}, [%4];"
                 : "=r"(r0), "=r"(r1), "=r"(r2), "=r"(r3) : "r"(addr));
}
DEV void mma_f16(float* d, const uint32_t* a, const uint32_t* b) {
    asm volatile(
        "mma.sync.aligned.m16n8k16.row.col.f32.f16.f16.f32 "
        "{%0,%1,%2,%3}, {%4,%5,%6,%7}, {%8,%9}, {%0,%1,%2,%3};"
        : "+f"(d[0]), "+f"(d[1]), "+f"(d[2]), "+f"(d[3])
        : "r"(a[0]), "r"(a[1]), "r"(a[2]), "r"(a[3]), "r"(b[0]), "r"(b[1]));
}
DEV uint32_t pack2(float lo, float hi) {
    __half2 h = __halves2half2(__float2half_rn(lo), __float2half_rn(hi));
    return *reinterpret_cast<uint32_t*>(&h);
}

// ---------------- prep: build 6 A-matrices (swizzled tile-major fp16) ----------------
__global__ void k_pack_x(const float* __restrict__ x) {
    size_t gci = (size_t)blockIdx.x * 256 + threadIdx.x;     // 6 * 1048576 chunks
    int a_idx = (int)(gci >> 20);
    int rem   = (int)(gci & 1048575);
    int t  = rem >> 10;                   // tile in matrix: mt*16 + kt
    int ci = rem & 1023;
    int mt = t >> 4, kt = t & 15;
    int row = ci >> 3, c = ci & 7;
    int row_g = mt * BM + row;
    int colbase = kt * BK + c * 8;        // within one 1024-wide component
    const float* base = x + (size_t)row_g * FEAT + colbase;
    float4 v0, v1;
    if (a_idx < 4) {
        const float4* s = reinterpret_cast<const float4*>(base + a_idx * Q);
        v0 = s[0]; v1 = s[1];
    } else {
        int c0 = (a_idx == 4) ? 0 : 2;
        const float4* s0 = reinterpret_cast<const float4*>(base + c0 * Q);
        const float4* s1 = reinterpret_cast<const float4*>(base + (c0 + 1) * Q);
        float4 p0 = s0[0], p1 = s0[1], q0 = s1[0], q1 = s1[1];
        v0 = make_float4(p0.x + q0.x, p0.y + q0.y, p0.z + q0.z, p0.w + q0.w);
        v1 = make_float4(p1.x + q1.x, p1.y + q1.y, p1.z + q1.z, p1.w + q1.w);
    }
    uint4 d;
    d.x = pack2(v0.x, v0.y); d.y = pack2(v0.z, v0.w);
    d.z = pack2(v1.x, v1.y); d.w = pack2(v1.z, v1.w);
    size_t dst = ((size_t)a_idx << 20) + ((size_t)t << 10) + (row << 3) + (c ^ (row & 7));
    reinterpret_cast<uint4*>(g_X)[dst] = d;
}

// ---------------- prep: build 12 B-matrices (W combos, signs folded) ----------------
__global__ void k_pack_w(const float* __restrict__ wrr, const float* __restrict__ wri,
                         const float* __restrict__ wrj, const float* __restrict__ wrk) {
    size_t gci = (size_t)blockIdx.x * 256 + threadIdx.x;     // 12 * 131072 chunks
    int b_idx = (int)(gci >> 17);
    int rem   = (int)(gci & 131071);
    int t  = rem >> 10;                   // nt*16 + kt
    int ci = rem & 1023;
    int row = ci >> 3, c = ci & 7;        // row = o-local, c = k-chunk
    int o = (t >> 4) * BN + row;
    int k = (t & 15) * BK + c * 8;
    // combos:              0    1    2    3    4      5      6    7    8    9    10     11
    //                     Wrr -Wrj  Wri  Wrk rr+ri  rk-rj   Wrj  Wrr  Wrk -Wri rj+rk  rr-ri
    const int   s1[12] = {  0,   2,   1,   3,   0,     3,     2,   0,   3,   1,   2,     0  };
    const float g1[12] = {  1,  -1,   1,   1,   1,     1,     1,   1,   1,  -1,   1,     1  };
    const int   s2[12] = { -1,  -1,  -1,  -1,   1,     2,    -1,  -1,  -1,  -1,   3,     1  };
    const float g2[12] = {  0,   0,   0,   0,   1,    -1,     0,   0,   0,   0,   1,    -1  };
    const float* srcs[4] = {wrr, wri, wrj, wrk};
    size_t off = (size_t)o * Q + k;
    const float4* sa = reinterpret_cast<const float4*>(srcs[s1[b_idx]] + off);
    float ga = g1[b_idx];
    float4 v0 = sa[0], v1 = sa[1];
    v0.x *= ga; v0.y *= ga; v0.z *= ga; v0.w *= ga;
    v1.x *= ga; v1.y *= ga; v1.z *= ga; v1.w *= ga;
    if (s2[b_idx] >= 0) {
        const float4* sb = reinterpret_cast<const float4*>(srcs[s2[b_idx]] + off);
        float gb = g2[b_idx];
        float4 q0 = sb[0], q1 = sb[1];
        v0.x += gb * q0.x; v0.y += gb * q0.y; v0.z += gb * q0.z; v0.w += gb * q0.w;
        v1.x += gb * q1.x; v1.y += gb * q1.y; v1.z += gb * q1.z; v1.w += gb * q1.w;
    }
    uint4 d;
    d.x = pack2(v0.x, v0.y); d.y = pack2(v0.z, v0.w);
    d.z = pack2(v1.x, v1.y); d.w = pack2(v1.z, v1.w);
    size_t dst = ((size_t)b_idx << 17) + ((size_t)t << 10) + (row << 3) + (c ^ (row & 7));
    reinterpret_cast<uint4*>(g_W)[dst] = d;
}

// ---------------- main kernel: 256 threads, 8 warps (2M x 4N), warp tile 64x32 ----
__global__ void __launch_bounds__(256, 1)
k_qdense(const float* __restrict__ brr, float* __restrict__ out) {
    extern __shared__ char smem[];
    uint32_t sb = smem_u32(smem);
    int tid = threadIdx.x, wid = tid >> 5, lane = tid & 31;
    int wm = wid >> 2, wn = wid & 3;

    int bid = blockIdx.x;
    int nt = bid & 7;
    int mt = (bid >> 3) & 63;
    int pc = bid >> 9;                 // 0: (out_r,out_i), 1: (out_j,out_k)

    if (tid == 0) {
#pragma unroll
        for (int s = 0; s < NSTAGE; s++) mbar_init(sb + SM_MBAR + 8 * s, 1);
    }
    __syncthreads();

    // phase -> A matrix selector (nibble-packed): {0,2,1,3,4,5}
    const uint32_t ASEL = 0x543120u;

    auto issue = [&](int it) {
        int ph = it >> 4, ktl = it & 15;
        int s = it % NSTAGE;
        uint32_t a_sel = (ASEL >> (ph * 4)) & 0xF;
        const __half* sa = g_X + ((((size_t)a_sel * MT + mt) * KT_PER_PHASE) + ktl) * TILE_HALVES;
        const __half* sw = g_W + ((((size_t)(pc * 6 + ph) * NT + nt) * KT_PER_PHASE) + ktl) * TILE_HALVES;
        uint32_t mb = sb + SM_MBAR + 8 * s;
        uint32_t st = sb + SM_DATA + s * STAGE_BYTES;
        mbar_expect_tx(mb, STAGE_BYTES);
        bulk_g2s(st,         sa, A_TILE_BYTES, mb);
        bulk_g2s(st + OFF_B, sw, B_TILE_BYTES, mb);
    };

    if (tid == 0) {
#pragma unroll
        for (int p = 0; p < NSTAGE - 1; p++) issue(p);
    }

    float acc[3][4][4][4];
#pragma unroll
    for (int a = 0; a < 3; a++)
#pragma unroll
        for (int i = 0; i < 4; i++)
#pragma unroll
            for (int j = 0; j < 4; j++)
#pragma unroll
                for (int v = 0; v < 4; v++) acc[a][i][j][v] = 0.0f;

    int a_rowl_base = ((lane >> 3) & 1) * 8 + (lane & 7);
    int a_chunk_sel = lane >> 4;
    int b_rowl_base = ((lane >> 4) << 3) + (lane & 7);
    int b_chunk_sel = (lane >> 3) & 1;

#pragma unroll
    for (int p = 0; p < 3; p++) {          // accumulator index (compile-time)
#pragma unroll 1
        for (int h = 0; h < 2; h++) {      // two phases per accumulator
#pragma unroll 1
            for (int ktl = 0; ktl < KT_PER_PHASE; ktl++) {
                int it = (p * 2 + h) * KT_PER_PHASE + ktl;
                int s = it % NSTAGE;
                uint32_t par = (uint32_t)((it / NSTAGE) & 1);
                __syncthreads();
                if (tid == 0 && it + (NSTAGE - 1) < TOTAL_IT) issue(it + (NSTAGE - 1));
                mbar_wait(sb + SM_MBAR + 8 * s, par);

                uint32_t abase = sb + SM_DATA + s * STAGE_BYTES + wm * (64 * 128);
                uint32_t bbase = sb + SM_DATA + s * STAGE_BYTES + OFF_B + wn * (32 * 128);
#pragma unroll
                for (int ks = 0; ks < 4; ks++) {
                    uint32_t a[4][4];
#pragma unroll
                    for (int mf = 0; mf < 4; mf++) {
                        int rowl = mf * 16 + a_rowl_base;
                        int chunk = ks * 2 + a_chunk_sel;
                        uint32_t addr = abase + rowl * 128 + ((chunk ^ (rowl & 7)) << 4);
                        ldsm4(a[mf][0], a[mf][1], a[mf][2], a[mf][3], addr);
                    }
                    uint32_t b[4][2];
#pragma unroll
                    for (int nf2 = 0; nf2 < 2; nf2++) {
                        int rowl = nf2 * 16 + b_rowl_base;
                        int chunk = ks * 2 + b_chunk_sel;
                        uint32_t addr = bbase + rowl * 128 + ((chunk ^ (rowl & 7)) << 4);
                        ldsm4(b[2 * nf2][0], b[2 * nf2][1], b[2 * nf2 + 1][0], b[2 * nf2 + 1][1], addr);
                    }
#pragma unroll
                    for (int mf = 0; mf < 4; mf++)
#pragma unroll
                        for (int nf = 0; nf < 4; nf++)
                            mma_f16(acc[p][mf][nf], a[mf], b[nf]);
                }
            }
        }
    }

    // ---------------- epilogue: combine 3 accumulators -> 2 output tiles ----------------
    // first  = accA - accB + bias   (out_r / out_j)
    // second = accC - accA - accB + bias  (out_i / out_k)
#pragma unroll
    for (int nf = 0; nf < 4; nf++) {
        int coll = wn * 32 + nf * 8 + (lane & 3) * 2;
        float bi0 = __ldg(brr + nt * BN + coll);
        float bi1 = __ldg(brr + nt * BN + coll + 1);
        size_t colR = (size_t)pc * 2048 + nt * BN + coll;
#pragma unroll
        for (int mf = 0; mf < 4; mf++) {
            size_t row0 = (size_t)mt * BM + wm * 64 + mf * 16 + (lane >> 2);
#pragma unroll
            for (int half = 0; half < 2; half++) {
                int v0 = half * 2, v1 = half * 2 + 1;
                size_t r = row0 + half * 8;
                float A0 = acc[0][mf][nf][v0], A1 = acc[0][mf][nf][v1];
                float B0 = acc[1][mf][nf][v0], B1 = acc[1][mf][nf][v1];
                float C0 = acc[2][mf][nf][v0], C1 = acc[2][mf][nf][v1];
                float2 vr = make_float2(A0 - B0 + bi0, A1 - B1 + bi1);
                float2 vi = make_float2(C0 - A0 - B0 + bi0, C1 - A1 - B1 + bi1);
                *reinterpret_cast<float2*>(out + r * FEAT + colR) = vr;
                *reinterpret_cast<float2*>(out + r * FEAT + colR + 1024) = vi;
            }
        }
    }
}

// ---------------- launch ----------------
extern "C" void kernel_launch(void* const* d_in, const int* in_sizes, int n_in,
                              void* d_out, int out_size) {
    const float* x   = (const float*)d_in[0];
    const float* wrr = (const float*)d_in[1];
    const float* wri = (const float*)d_in[2];
    const float* wrj = (const float*)d_in[3];
    const float* wrk = (const float*)d_in[4];
    const float* brr = (const float*)d_in[5];
    float* out = (float*)d_out;

    k_pack_x<<<6 * 1048576 / 256, 256>>>(x);
    k_pack_w<<<12 * 131072 / 256, 256>>>(wrr, wri, wrj, wrk);

    cudaFuncSetAttribute(k_qdense, cudaFuncAttributeMaxDynamicSharedMemorySize, SMEM_TOTAL);
    k_qdense<<<2 * MT * NT, 256, SMEM_TOTAL>>>(brr, out);
}

// round 5
// speedup vs baseline: 2.4625x; 1.1172x over previous
#include <cuda_runtime.h>
#include <cuda_fp16.h>
#include <cstdint>
#include <cstddef>

#define DEV __device__ __forceinline__

// ---------------- problem dims ----------------
constexpr int BATCH = 8192;
constexpr int FEAT  = 4096;
constexpr int Q     = 1024;

// ---------------- tiling ----------------
constexpr int BM = 128;
constexpr int BN = 128;
constexpr int BK = 128;                   // fp16 per k-tile (256B rows, 16 chunks)
constexpr int KT_PER_PHASE = Q / BK;      // 8
constexpr int TOTAL_IT = 6 * KT_PER_PHASE;// 48
constexpr int NSTAGE = 3;

constexpr int A_TILE_BYTES = BM * BK * 2; // 32768
constexpr int B_TILE_BYTES = BN * BK * 2; // 32768
constexpr int OFF_B = A_TILE_BYTES;
constexpr int STAGE_BYTES = A_TILE_BYTES + B_TILE_BYTES;       // 65536

constexpr int SM_MBAR = 0;
constexpr int SM_DATA = 1024;
constexpr int SMEM_TOTAL = SM_DATA + NSTAGE * STAGE_BYTES;     // 197632

constexpr int MT = BATCH / BM;            // 64
constexpr int NT = Q / BN;                // 8

constexpr int TILE_HALVES = BM * BK;      // 16384 (128x128)

// ---------------- device scratch ----------------
// g_X: 6 A-matrices (x0,x1,x2,x3,x0+x1,x2+x3): [a(6)][mt(64)][ktl(8)] 32KB tiles, swizzled
// g_W: 12 B-matrices (W combos, signs folded): [b(12)][nt(8)][ktl(8)] 32KB tiles
__device__ __half g_X[(size_t)6 * BATCH * Q];
__device__ __half g_W[(size_t)12 * Q * Q];

// ---------------- helpers ----------------
DEV uint32_t smem_u32(const void* p) {
    uint32_t a;
    asm("{ .reg .u64 t; cvta.to.shared.u64 t, %1; cvt.u32.u64 %0, t; }" : "=r"(a) : "l"(p));
    return a;
}
DEV void mbar_init(uint32_t a, uint32_t cnt) {
    asm volatile("mbarrier.init.shared.b64 [%0], %1;" :: "r"(a), "r"(cnt) : "memory");
}
DEV void mbar_expect_tx(uint32_t a, uint32_t bytes) {
    asm volatile("mbarrier.arrive.expect_tx.shared.b64 _, [%0], %1;"
                 :: "r"(a), "r"(bytes) : "memory");
}
DEV void mbar_wait(uint32_t a, uint32_t parity) {
    asm volatile(
        "{\n\t.reg .pred P;\n\t"
        "WL%=:\n\t"
        "mbarrier.try_wait.parity.acquire.cta.shared::cta.b64 P, [%0], %1, 0x989680;\n\t"
        "@P bra.uni WD%=;\n\t"
        "bra.uni WL%=;\n\t"
        "WD%=:\n\t}"
        :: "r"(a), "r"(parity) : "memory");
}
DEV void bulk_g2s(uint32_t dst, const void* src, uint32_t bytes, uint32_t mbar) {
    asm volatile(
        "cp.async.bulk.shared::cluster.global.mbarrier::complete_tx::bytes [%0], [%1], %2, [%3];"
        :: "r"(dst), "l"(src), "r"(bytes), "r"(mbar) : "memory");
}
DEV void ldsm4(uint32_t& r0, uint32_t& r1, uint32_t& r2, uint32_t& r3, uint32_t addr) {
    asm volatile("ldmatrix.sync.aligned.m8n8.x4.shared.b16 {%0,%1,%2,%3}, [%4];"
                 : "=r"(r0), "=r"(r1), "=r"(r2), "=r"(r3) : "r"(addr));
}
DEV void mma_f16(float* d, const uint32_t* a, const uint32_t* b) {
    asm volatile(
        "mma.sync.aligned.m16n8k16.row.col.f32.f16.f16.f32 "
        "{%0,%1,%2,%3}, {%4,%5,%6,%7}, {%8,%9}, {%0,%1,%2,%3};"
        : "+f"(d[0]), "+f"(d[1]), "+f"(d[2]), "+f"(d[3])
        : "r"(a[0]), "r"(a[1]), "r"(a[2]), "r"(a[3]), "r"(b[0]), "r"(b[1]));
}
DEV uint32_t pack2(float lo, float hi) {
    __half2 h = __halves2half2(__float2half_rn(lo), __float2half_rn(hi));
    return *reinterpret_cast<uint32_t*>(&h);
}

// ---------------- prep: build 6 A-matrices, fused (read x once) ----------------
// tile = 128 rows x 128 halves = 2048 x 16B chunks; phys chunk = row*16 + (c ^ (row&7))
__global__ void k_pack_x(const float* __restrict__ x) {
    size_t gci = (size_t)blockIdx.x * 256 + threadIdx.x;     // 2^20 chunk-slots
    int t  = (int)(gci >> 11);            // 0..511 = mt*8 + ktl
    int ci = (int)(gci & 2047);
    int mt = t >> 3, ktl = t & 7;
    int row = ci >> 4, c = ci & 15;
    const float* base = x + (size_t)(mt * 128 + row) * FEAT + ktl * 128 + c * 8;
    float4 v[4][2];
#pragma unroll
    for (int j = 0; j < 4; j++) {
        const float4* s = reinterpret_cast<const float4*>(base + j * Q);
        v[j][0] = s[0]; v[j][1] = s[1];
    }
    uint4 d[6];
#pragma unroll
    for (int j = 0; j < 4; j++) {
        d[j].x = pack2(v[j][0].x, v[j][0].y); d[j].y = pack2(v[j][0].z, v[j][0].w);
        d[j].z = pack2(v[j][1].x, v[j][1].y); d[j].w = pack2(v[j][1].z, v[j][1].w);
    }
    d[4].x = pack2(v[0][0].x + v[1][0].x, v[0][0].y + v[1][0].y);
    d[4].y = pack2(v[0][0].z + v[1][0].z, v[0][0].w + v[1][0].w);
    d[4].z = pack2(v[0][1].x + v[1][1].x, v[0][1].y + v[1][1].y);
    d[4].w = pack2(v[0][1].z + v[1][1].z, v[0][1].w + v[1][1].w);
    d[5].x = pack2(v[2][0].x + v[3][0].x, v[2][0].y + v[3][0].y);
    d[5].y = pack2(v[2][0].z + v[3][0].z, v[2][0].w + v[3][0].w);
    d[5].z = pack2(v[2][1].x + v[3][1].x, v[2][1].y + v[3][1].y);
    d[5].w = pack2(v[2][1].z + v[3][1].z, v[2][1].w + v[3][1].w);
    size_t dstbase = ((size_t)t << 11) + (row << 4) + (c ^ (row & 7));
    uint4* o = reinterpret_cast<uint4*>(g_X);
#pragma unroll
    for (int j = 0; j < 6; j++) o[((size_t)j << 20) + dstbase] = d[j];
}

// ---------------- prep: build 12 B-matrices (W combos, signs folded) ----------------
__global__ void k_pack_w(const float* __restrict__ wrr, const float* __restrict__ wri,
                         const float* __restrict__ wrj, const float* __restrict__ wrk) {
    size_t gci = (size_t)blockIdx.x * 256 + threadIdx.x;     // 12 * 2^17 chunks
    int b_idx = (int)(gci >> 17);
    int rem   = (int)(gci & 131071);
    int t  = rem >> 11;                   // 0..63 = nt*8 + ktl
    int ci = rem & 2047;
    int row = ci >> 4, c = ci & 15;
    int o = (t >> 3) * 128 + row;
    int k = (t & 7) * 128 + c * 8;
    // combos:              0    1    2    3    4      5      6    7    8    9    10     11
    //                     Wrr -Wrj  Wri  Wrk rr+ri  rk-rj   Wrj  Wrr  Wrk -Wri rj+rk  rr-ri
    const int   s1[12] = {  0,   2,   1,   3,   0,     3,     2,   0,   3,   1,   2,     0  };
    const float g1[12] = {  1,  -1,   1,   1,   1,     1,     1,   1,   1,  -1,   1,     1  };
    const int   s2[12] = { -1,  -1,  -1,  -1,   1,     2,    -1,  -1,  -1,  -1,   3,     1  };
    const float g2[12] = {  0,   0,   0,   0,   1,    -1,     0,   0,   0,   0,   1,    -1  };
    const float* srcs[4] = {wrr, wri, wrj, wrk};
    size_t off = (size_t)o * Q + k;
    const float4* sa = reinterpret_cast<const float4*>(srcs[s1[b_idx]] + off);
    float ga = g1[b_idx];
    float4 v0 = sa[0], v1 = sa[1];
    v0.x *= ga; v0.y *= ga; v0.z *= ga; v0.w *= ga;
    v1.x *= ga; v1.y *= ga; v1.z *= ga; v1.w *= ga;
    if (s2[b_idx] >= 0) {
        const float4* sb = reinterpret_cast<const float4*>(srcs[s2[b_idx]] + off);
        float gb = g2[b_idx];
        float4 q0 = sb[0], q1 = sb[1];
        v0.x += gb * q0.x; v0.y += gb * q0.y; v0.z += gb * q0.z; v0.w += gb * q0.w;
        v1.x += gb * q1.x; v1.y += gb * q1.y; v1.z += gb * q1.z; v1.w += gb * q1.w;
    }
    uint4 d;
    d.x = pack2(v0.x, v0.y); d.y = pack2(v0.z, v0.w);
    d.z = pack2(v1.x, v1.y); d.w = pack2(v1.z, v1.w);
    size_t dst = ((size_t)b_idx << 17) + ((size_t)t << 11) + (row << 4) + (c ^ (row & 7));
    reinterpret_cast<uint4*>(g_W)[dst] = d;
}

// ---------------- main kernel: 256 threads, 8 warps (2M x 4N), warp tile 64x32 ----
__global__ void __launch_bounds__(256, 1)
k_qdense(const float* __restrict__ brr, float* __restrict__ out) {
    extern __shared__ char smem[];
    uint32_t sb = smem_u32(smem);
    int tid = threadIdx.x, wid = tid >> 5, lane = tid & 31;
    int wm = wid >> 2, wn = wid & 3;

    int bid = blockIdx.x;
    int nt = bid & 7;
    int mt = (bid >> 3) & 63;
    int pc = bid >> 9;                 // 0: (out_r,out_i), 1: (out_j,out_k)

    if (tid == 0) {
#pragma unroll
        for (int s = 0; s < NSTAGE; s++) mbar_init(sb + SM_MBAR + 8 * s, 1);
    }
    __syncthreads();

    // phase -> A matrix selector (nibble-packed): {0,2,1,3,4,5}
    const uint32_t ASEL = 0x543120u;

    auto issue = [&](int it) {
        int ph = it >> 3, ktl = it & 7;
        int s = it % NSTAGE;
        uint32_t a_sel = (ASEL >> (ph * 4)) & 0xF;
        const __half* sa = g_X + ((size_t)a_sel << 23) + ((size_t)(mt * 8 + ktl) << 14);
        const __half* sw = g_W + ((size_t)(pc * 6 + ph) << 20) + ((size_t)(nt * 8 + ktl) << 14);
        uint32_t mb = sb + SM_MBAR + 8 * s;
        uint32_t st = sb + SM_DATA + s * STAGE_BYTES;
        mbar_expect_tx(mb, STAGE_BYTES);
        bulk_g2s(st,         sa, A_TILE_BYTES, mb);
        bulk_g2s(st + OFF_B, sw, B_TILE_BYTES, mb);
    };

    if (tid == 0) { issue(0); issue(1); }

    float acc0[4][4][4], acc1[4][4][4];
#pragma unroll
    for (int i = 0; i < 4; i++)
#pragma unroll
        for (int j = 0; j < 4; j++)
#pragma unroll
            for (int v = 0; v < 4; v++) { acc0[i][j][v] = 0.0f; acc1[i][j][v] = 0.0f; }

    int a_rowl_base = ((lane >> 3) & 1) * 8 + (lane & 7);
    int a_chunk_sel = lane >> 4;
    int b_rowl_base = ((lane >> 4) << 3) + (lane & 7);
    int b_chunk_sel = (lane >> 3) & 1;

    auto do_kt = [&](int it, float (*acc)[4][4]) {
        int s = it % NSTAGE;
        uint32_t par = (uint32_t)((it / NSTAGE) & 1);
        __syncthreads();                                // all warps done with stage (it-1)%3
        if (tid == 0 && it + 2 < TOTAL_IT) issue(it + 2);
        mbar_wait(sb + SM_MBAR + 8 * s, par);

        uint32_t abase = sb + SM_DATA + s * STAGE_BYTES + wm * (64 * 256);
        uint32_t bbase = sb + SM_DATA + s * STAGE_BYTES + OFF_B + wn * (32 * 256);
#pragma unroll
        for (int ks = 0; ks < 8; ks++) {                // 8 x k16 per k-tile
            uint32_t a[4][4];
#pragma unroll
            for (int mf = 0; mf < 4; mf++) {
                int rowl = mf * 16 + a_rowl_base;
                int chunk = ks * 2 + a_chunk_sel;
                uint32_t addr = abase + rowl * 256 + ((chunk ^ (rowl & 7)) << 4);
                ldsm4(a[mf][0], a[mf][1], a[mf][2], a[mf][3], addr);
            }
            uint32_t b[4][2];
#pragma unroll
            for (int nf2 = 0; nf2 < 2; nf2++) {
                int rowl = nf2 * 16 + b_rowl_base;
                int chunk = ks * 2 + b_chunk_sel;
                uint32_t addr = bbase + rowl * 256 + ((chunk ^ (rowl & 7)) << 4);
                ldsm4(b[2 * nf2][0], b[2 * nf2][1], b[2 * nf2 + 1][0], b[2 * nf2 + 1][1], addr);
            }
#pragma unroll
            for (int mf = 0; mf < 4; mf++)
#pragma unroll
                for (int nf = 0; nf < 4; nf++)
                    mma_f16(acc[mf][nf], a[mf], b[nf]);
        }
    };

    // segment 0: phases 0,1 -> acc0 (accA)
#pragma unroll 1
    for (int it = 0; it < 16; it++) do_kt(it, acc0);
    // segment 1: phases 2,3 -> acc1 (accB)
#pragma unroll 1
    for (int it = 16; it < 32; it++) do_kt(it, acc1);

    // bias (per-lane columns)
    float bia[4][2];
#pragma unroll
    for (int nf = 0; nf < 4; nf++) {
        int coll = wn * 32 + nf * 8 + (lane & 3) * 2;
        bia[nf][0] = __ldg(brr + nt * BN + coll);
        bia[nf][1] = __ldg(brr + nt * BN + coll + 1);
    }

    // mid epilogue: out_first = A - B + bias; then acc0 = A + B (T), acc1 = 0
    {
        size_t colR = (size_t)pc * 2048 + nt * BN;
#pragma unroll
        for (int nf = 0; nf < 4; nf++) {
            int coll = wn * 32 + nf * 8 + (lane & 3) * 2;
#pragma unroll
            for (int mf = 0; mf < 4; mf++) {
                size_t row0 = (size_t)mt * BM + wm * 64 + mf * 16 + (lane >> 2);
#pragma unroll
                for (int h = 0; h < 2; h++) {
                    int v0 = h * 2, v1 = h * 2 + 1;
                    float2 vr = make_float2(acc0[mf][nf][v0] - acc1[mf][nf][v0] + bia[nf][0],
                                            acc0[mf][nf][v1] - acc1[mf][nf][v1] + bia[nf][1]);
                    *reinterpret_cast<float2*>(out + (row0 + h * 8) * FEAT + colR + coll) = vr;
                }
            }
        }
#pragma unroll
        for (int i = 0; i < 4; i++)
#pragma unroll
            for (int j = 0; j < 4; j++)
#pragma unroll
                for (int v = 0; v < 4; v++) {
                    acc0[i][j][v] += acc1[i][j][v];     // T = A + B
                    acc1[i][j][v] = 0.0f;
                }
    }

    // segment 2: phases 4,5 -> acc1 (accC)
#pragma unroll 1
    for (int it = 32; it < 48; it++) do_kt(it, acc1);

    // final epilogue: out_second = C - T + bias
    {
        size_t colR = (size_t)pc * 2048 + nt * BN + 1024;
#pragma unroll
        for (int nf = 0; nf < 4; nf++) {
            int coll = wn * 32 + nf * 8 + (lane & 3) * 2;
#pragma unroll
            for (int mf = 0; mf < 4; mf++) {
                size_t row0 = (size_t)mt * BM + wm * 64 + mf * 16 + (lane >> 2);
#pragma unroll
                for (int h = 0; h < 2; h++) {
                    int v0 = h * 2, v1 = h * 2 + 1;
                    float2 vi = make_float2(acc1[mf][nf][v0] - acc0[mf][nf][v0] + bia[nf][0],
                                            acc1[mf][nf][v1] - acc0[mf][nf][v1] + bia[nf][1]);
                    *reinterpret_cast<float2*>(out + (row0 + h * 8) * FEAT + colR + coll) = vi;
                }
            }
        }
    }
}

// ---------------- launch ----------------
extern "C" void kernel_launch(void* const* d_in, const int* in_sizes, int n_in,
                              void* d_out, int out_size) {
    const float* x   = (const float*)d_in[0];
    const float* wrr = (const float*)d_in[1];
    const float* wri = (const float*)d_in[2];
    const float* wrj = (const float*)d_in[3];
    const float* wrk = (const float*)d_in[4];
    const float* brr = (const float*)d_in[5];
    float* out = (float*)d_out;

    k_pack_x<<<(1 << 20) / 256, 256>>>(x);
    k_pack_w<<<12 * 131072 / 256, 256>>>(wrr, wri, wrj, wrk);

    cudaFuncSetAttribute(k_qdense, cudaFuncAttributeMaxDynamicSharedMemorySize, SMEM_TOTAL);
    k_qdense<<<2 * MT * NT, 256, SMEM_TOTAL>>>(brr, out);
}

// round 6
// speedup vs baseline: 2.7385x; 1.1121x over previous
#include <cuda_runtime.h>
#include <cuda_fp16.h>
#include <cstdint>
#include <cstddef>

#define DEV __device__ __forceinline__

// ---------------- problem dims ----------------
constexpr int BATCH = 8192;
constexpr int FEAT  = 4096;
constexpr int Q     = 1024;

// ---------------- tiling ----------------
constexpr int BM = 128;
constexpr int BN = 128;
constexpr int BK = 128;                   // fp16 per k-tile (256B rows, 16 chunks)
constexpr int KT_PER_PHASE = Q / BK;      // 8
constexpr int TOTAL_IT = 6 * KT_PER_PHASE;// 48
constexpr int NSTAGE = 3;

constexpr int A_TILE_BYTES = BM * BK * 2; // 32768
constexpr int B_TILE_BYTES = BN * BK * 2; // 32768
constexpr int OFF_B = A_TILE_BYTES;
constexpr int STAGE_BYTES = A_TILE_BYTES + B_TILE_BYTES;       // 65536

constexpr int SM_FULL  = 0;               // 3 x 8B
constexpr int SM_EMPTY = 64;              // 3 x 8B
constexpr int SM_DATA  = 1024;
constexpr int SMEM_TOTAL = SM_DATA + NSTAGE * STAGE_BYTES;     // 197632

constexpr int MT = BATCH / BM;            // 64
constexpr int NT = Q / BN;                // 8

// ---------------- device scratch ----------------
// g_X: 6 A-matrices (x0,x1,x2,x3,x0+x1,x2+x3): [a(6)][mt(64)][ktl(8)] 32KB tiles, swizzled
// g_W: 12 B-matrices (W combos, signs folded): [b(12)][nt(8)][ktl(8)] 32KB tiles
__device__ __half g_X[(size_t)6 * BATCH * Q];
__device__ __half g_W[(size_t)12 * Q * Q];

// ---------------- helpers ----------------
DEV uint32_t smem_u32(const void* p) {
    uint32_t a;
    asm("{ .reg .u64 t; cvta.to.shared.u64 t, %1; cvt.u32.u64 %0, t; }" : "=r"(a) : "l"(p));
    return a;
}
DEV void mbar_init(uint32_t a, uint32_t cnt) {
    asm volatile("mbarrier.init.shared.b64 [%0], %1;" :: "r"(a), "r"(cnt) : "memory");
}
DEV void mbar_expect_tx(uint32_t a, uint32_t bytes) {
    asm volatile("mbarrier.arrive.expect_tx.shared.b64 _, [%0], %1;"
                 :: "r"(a), "r"(bytes) : "memory");
}
DEV void mbar_arrive(uint32_t a) {
    asm volatile("mbarrier.arrive.shared.b64 _, [%0];" :: "r"(a) : "memory");
}
DEV void mbar_wait(uint32_t a, uint32_t parity) {
    asm volatile(
        "{\n\t.reg .pred P;\n\t"
        "WL%=:\n\t"
        "mbarrier.try_wait.parity.acquire.cta.shared::cta.b64 P, [%0], %1, 0x989680;\n\t"
        "@P bra.uni WD%=;\n\t"
        "bra.uni WL%=;\n\t"
        "WD%=:\n\t}"
        :: "r"(a), "r"(parity) : "memory");
}
DEV void bulk_g2s(uint32_t dst, const void* src, uint32_t bytes, uint32_t mbar) {
    asm volatile(
        "cp.async.bulk.shared::cluster.global.mbarrier::complete_tx::bytes [%0], [%1], %2, [%3];"
        :: "r"(dst), "l"(src), "r"(bytes), "r"(mbar) : "memory");
}
DEV void ldsm4(uint32_t& r0, uint32_t& r1, uint32_t& r2, uint32_t& r3, uint32_t addr) {
    asm volatile("ldmatrix.sync.aligned.m8n8.x4.shared.b16 {%0,%1,%2,%3}, [%4];"
                 : "=r"(r0), "=r"(r1), "=r"(r2), "=r"(r3) : "r"(addr));
}
DEV void mma_f16(float* d, const uint32_t* a, const uint32_t* b) {
    asm volatile(
        "mma.sync.aligned.m16n8k16.row.col.f32.f16.f16.f32 "
        "{%0,%1,%2,%3}, {%4,%5,%6,%7}, {%8,%9}, {%0,%1,%2,%3};"
        : "+f"(d[0]), "+f"(d[1]), "+f"(d[2]), "+f"(d[3])
        : "r"(a[0]), "r"(a[1]), "r"(a[2]), "r"(a[3]), "r"(b[0]), "r"(b[1]));
}
DEV uint32_t pack2(float lo, float hi) {
    __half2 h = __halves2half2(__float2half_rn(lo), __float2half_rn(hi));
    return *reinterpret_cast<uint32_t*>(&h);
}

// ---------------- prep: build 6 A-matrices, fused (read x once) ----------------
// tile = 128 rows x 128 halves = 2048 x 16B chunks; phys chunk = row*16 + (c ^ (row&7))
__global__ void k_pack_x(const float* __restrict__ x) {
    size_t gci = (size_t)blockIdx.x * 256 + threadIdx.x;     // 2^20 chunk-slots
    int t  = (int)(gci >> 11);            // 0..511 = mt*8 + ktl
    int ci = (int)(gci & 2047);
    int mt = t >> 3, ktl = t & 7;
    int row = ci >> 4, c = ci & 15;
    const float* base = x + (size_t)(mt * 128 + row) * FEAT + ktl * 128 + c * 8;
    float4 v[4][2];
#pragma unroll
    for (int j = 0; j < 4; j++) {
        const float4* s = reinterpret_cast<const float4*>(base + j * Q);
        v[j][0] = s[0]; v[j][1] = s[1];
    }
    uint4 d[6];
#pragma unroll
    for (int j = 0; j < 4; j++) {
        d[j].x = pack2(v[j][0].x, v[j][0].y); d[j].y = pack2(v[j][0].z, v[j][0].w);
        d[j].z = pack2(v[j][1].x, v[j][1].y); d[j].w = pack2(v[j][1].z, v[j][1].w);
    }
    d[4].x = pack2(v[0][0].x + v[1][0].x, v[0][0].y + v[1][0].y);
    d[4].y = pack2(v[0][0].z + v[1][0].z, v[0][0].w + v[1][0].w);
    d[4].z = pack2(v[0][1].x + v[1][1].x, v[0][1].y + v[1][1].y);
    d[4].w = pack2(v[0][1].z + v[1][1].z, v[0][1].w + v[1][1].w);
    d[5].x = pack2(v[2][0].x + v[3][0].x, v[2][0].y + v[3][0].y);
    d[5].y = pack2(v[2][0].z + v[3][0].z, v[2][0].w + v[3][0].w);
    d[5].z = pack2(v[2][1].x + v[3][1].x, v[2][1].y + v[3][1].y);
    d[5].w = pack2(v[2][1].z + v[3][1].z, v[2][1].w + v[3][1].w);
    size_t dstbase = ((size_t)t << 11) + (row << 4) + (c ^ (row & 7));
    uint4* o = reinterpret_cast<uint4*>(g_X);
#pragma unroll
    for (int j = 0; j < 6; j++) o[((size_t)j << 20) + dstbase] = d[j];
}

// ---------------- prep: build 12 B-matrices (W combos, signs folded) ----------------
__global__ void k_pack_w(const float* __restrict__ wrr, const float* __restrict__ wri,
                         const float* __restrict__ wrj, const float* __restrict__ wrk) {
    size_t gci = (size_t)blockIdx.x * 256 + threadIdx.x;     // 12 * 2^17 chunks
    int b_idx = (int)(gci >> 17);
    int rem   = (int)(gci & 131071);
    int t  = rem >> 11;                   // 0..63 = nt*8 + ktl
    int ci = rem & 2047;
    int row = ci >> 4, c = ci & 15;
    int o = (t >> 3) * 128 + row;
    int k = (t & 7) * 128 + c * 8;
    // combos:              0    1    2    3    4      5      6    7    8    9    10     11
    //                     Wrr -Wrj  Wri  Wrk rr+ri  rk-rj   Wrj  Wrr  Wrk -Wri rj+rk  rr-ri
    const int   s1[12] = {  0,   2,   1,   3,   0,     3,     2,   0,   3,   1,   2,     0  };
    const float g1[12] = {  1,  -1,   1,   1,   1,     1,     1,   1,   1,  -1,   1,     1  };
    const int   s2[12] = { -1,  -1,  -1,  -1,   1,     2,    -1,  -1,  -1,  -1,   3,     1  };
    const float g2[12] = {  0,   0,   0,   0,   1,    -1,     0,   0,   0,   0,   1,    -1  };
    const float* srcs[4] = {wrr, wri, wrj, wrk};
    size_t off = (size_t)o * Q + k;
    const float4* sa = reinterpret_cast<const float4*>(srcs[s1[b_idx]] + off);
    float ga = g1[b_idx];
    float4 v0 = sa[0], v1 = sa[1];
    v0.x *= ga; v0.y *= ga; v0.z *= ga; v0.w *= ga;
    v1.x *= ga; v1.y *= ga; v1.z *= ga; v1.w *= ga;
    if (s2[b_idx] >= 0) {
        const float4* sb = reinterpret_cast<const float4*>(srcs[s2[b_idx]] + off);
        float gb = g2[b_idx];
        float4 q0 = sb[0], q1 = sb[1];
        v0.x += gb * q0.x; v0.y += gb * q0.y; v0.z += gb * q0.z; v0.w += gb * q0.w;
        v1.x += gb * q1.x; v1.y += gb * q1.y; v1.z += gb * q1.z; v1.w += gb * q1.w;
    }
    uint4 d;
    d.x = pack2(v0.x, v0.y); d.y = pack2(v0.z, v0.w);
    d.z = pack2(v1.x, v1.y); d.w = pack2(v1.z, v1.w);
    size_t dst = ((size_t)b_idx << 17) + ((size_t)t << 11) + (row << 4) + (c ^ (row & 7));
    reinterpret_cast<uint4*>(g_W)[dst] = d;
}

// ---------------- main kernel: 256 threads, 8 warps (2M x 4N), warp tile 64x32 ----
__global__ void __launch_bounds__(256, 1)
k_qdense(const float* __restrict__ brr, float* __restrict__ out) {
    extern __shared__ char smem[];
    uint32_t sb = smem_u32(smem);
    int tid = threadIdx.x, wid = tid >> 5, lane = tid & 31;
    int wm = wid >> 2, wn = wid & 3;

    int bid = blockIdx.x;
    int nt = bid & 7;
    int mt = (bid >> 3) & 63;
    int pc = bid >> 9;                 // 0: (out_r,out_i), 1: (out_j,out_k)

    if (tid == 0) {
#pragma unroll
        for (int s = 0; s < NSTAGE; s++) {
            mbar_init(sb + SM_FULL  + 8 * s, 1);   // expect_tx-driven
            mbar_init(sb + SM_EMPTY + 8 * s, 8);   // one arrive per warp
        }
    }
    __syncthreads();

    // phase -> A matrix selector (nibble-packed): {0,2,1,3,4,5}
    const uint32_t ASEL = 0x543120u;

    // producer: wait stage empty (flip-phase: first wrap passes immediately), then bulk-issue
    auto produce = [&](int ip) {
        int s = ip % NSTAGE;
        mbar_wait(sb + SM_EMPTY + 8 * s, (uint32_t)(((ip / NSTAGE) ^ 1) & 1));
        int ph = ip >> 3, ktl = ip & 7;
        uint32_t a_sel = (ASEL >> (ph * 4)) & 0xF;
        const __half* sa = g_X + ((size_t)a_sel << 23) + ((size_t)(mt * 8 + ktl) << 14);
        const __half* sw = g_W + ((size_t)(pc * 6 + ph) << 20) + ((size_t)(nt * 8 + ktl) << 14);
        uint32_t mb = sb + SM_FULL + 8 * s;
        uint32_t st = sb + SM_DATA + s * STAGE_BYTES;
        mbar_expect_tx(mb, STAGE_BYTES);
        bulk_g2s(st,         sa, A_TILE_BYTES, mb);
        bulk_g2s(st + OFF_B, sw, B_TILE_BYTES, mb);
    };

    if (tid == 0) { produce(0); produce(1); }

    float acc0[4][4][4], acc1[4][4][4];
#pragma unroll
    for (int i = 0; i < 4; i++)
#pragma unroll
        for (int j = 0; j < 4; j++)
#pragma unroll
            for (int v = 0; v < 4; v++) { acc0[i][j][v] = 0.0f; acc1[i][j][v] = 0.0f; }

    int a_rowl_base = ((lane >> 3) & 1) * 8 + (lane & 7);
    int a_chunk_sel = lane >> 4;
    int b_rowl_base = ((lane >> 4) << 3) + (lane & 7);
    int b_chunk_sel = (lane >> 3) & 1;

    auto do_kt = [&](int it, float (*acc)[4][4]) {
        int s = it % NSTAGE;
        if (tid == 0 && it + 2 < TOTAL_IT) produce(it + 2);
        mbar_wait(sb + SM_FULL + 8 * s, (uint32_t)((it / NSTAGE) & 1));

        uint32_t abase = sb + SM_DATA + s * STAGE_BYTES + wm * (64 * 256);
        uint32_t bbase = sb + SM_DATA + s * STAGE_BYTES + OFF_B + wn * (32 * 256);
#pragma unroll
        for (int ks = 0; ks < 8; ks++) {                // 8 x k16 per k-tile
            uint32_t a[4][4];
#pragma unroll
            for (int mf = 0; mf < 4; mf++) {
                int rowl = mf * 16 + a_rowl_base;
                int chunk = ks * 2 + a_chunk_sel;
                uint32_t addr = abase + rowl * 256 + ((chunk ^ (rowl & 7)) << 4);
                ldsm4(a[mf][0], a[mf][1], a[mf][2], a[mf][3], addr);
            }
            uint32_t b[4][2];
#pragma unroll
            for (int nf2 = 0; nf2 < 2; nf2++) {
                int rowl = nf2 * 16 + b_rowl_base;
                int chunk = ks * 2 + b_chunk_sel;
                uint32_t addr = bbase + rowl * 256 + ((chunk ^ (rowl & 7)) << 4);
                ldsm4(b[2 * nf2][0], b[2 * nf2][1], b[2 * nf2 + 1][0], b[2 * nf2 + 1][1], addr);
            }
#pragma unroll
            for (int mf = 0; mf < 4; mf++)
#pragma unroll
                for (int nf = 0; nf < 4; nf++)
                    mma_f16(acc[mf][nf], a[mf], b[nf]);
        }
        if (lane == 0) mbar_arrive(sb + SM_EMPTY + 8 * s);  // this warp done with stage s
    };

    // segment 0: phases 0,1 -> acc0 (accA)
#pragma unroll 1
    for (int it = 0; it < 16; it++) do_kt(it, acc0);
    // segment 1: phases 2,3 -> acc1 (accB)
#pragma unroll 1
    for (int it = 16; it < 32; it++) do_kt(it, acc1);

    // bias (per-lane columns)
    float bia[4][2];
#pragma unroll
    for (int nf = 0; nf < 4; nf++) {
        int coll = wn * 32 + nf * 8 + (lane & 3) * 2;
        bia[nf][0] = __ldg(brr + nt * BN + coll);
        bia[nf][1] = __ldg(brr + nt * BN + coll + 1);
    }

    // mid epilogue: out_first = A - B + bias; then acc0 = A + B (T), acc1 = 0
    {
        size_t colR = (size_t)pc * 2048 + nt * BN;
#pragma unroll
        for (int nf = 0; nf < 4; nf++) {
            int coll = wn * 32 + nf * 8 + (lane & 3) * 2;
#pragma unroll
            for (int mf = 0; mf < 4; mf++) {
                size_t row0 = (size_t)mt * BM + wm * 64 + mf * 16 + (lane >> 2);
#pragma unroll
                for (int h = 0; h < 2; h++) {
                    int v0 = h * 2, v1 = h * 2 + 1;
                    float2 vr = make_float2(acc0[mf][nf][v0] - acc1[mf][nf][v0] + bia[nf][0],
                                            acc0[mf][nf][v1] - acc1[mf][nf][v1] + bia[nf][1]);
                    *reinterpret_cast<float2*>(out + (row0 + h * 8) * FEAT + colR + coll) = vr;
                }
            }
        }
#pragma unroll
        for (int i = 0; i < 4; i++)
#pragma unroll
            for (int j = 0; j < 4; j++)
#pragma unroll
                for (int v = 0; v < 4; v++) {
                    acc0[i][j][v] += acc1[i][j][v];     // T = A + B
                    acc1[i][j][v] = 0.0f;
                }
    }

    // segment 2: phases 4,5 -> acc1 (accC)
#pragma unroll 1
    for (int it = 32; it < 48; it++) do_kt(it, acc1);

    // final epilogue: out_second = C - T + bias
    {
        size_t colR = (size_t)pc * 2048 + nt * BN + 1024;
#pragma unroll
        for (int nf = 0; nf < 4; nf++) {
            int coll = wn * 32 + nf * 8 + (lane & 3) * 2;
#pragma unroll
            for (int mf = 0; mf < 4; mf++) {
                size_t row0 = (size_t)mt * BM + wm * 64 + mf * 16 + (lane >> 2);
#pragma unroll
                for (int h = 0; h < 2; h++) {
                    int v0 = h * 2, v1 = h * 2 + 1;
                    float2 vi = make_float2(acc1[mf][nf][v0] - acc0[mf][nf][v0] + bia[nf][0],
                                            acc1[mf][nf][v1] - acc0[mf][nf][v1] + bia[nf][1]);
                    *reinterpret_cast<float2*>(out + (row0 + h * 8) * FEAT + colR + coll) = vi;
                }
            }
        }
    }
}

// ---------------- launch ----------------
extern "C" void kernel_launch(void* const* d_in, const int* in_sizes, int n_in,
                              void* d_out, int out_size) {
    const float* x   = (const float*)d_in[0];
    const float* wrr = (const float*)d_in[1];
    const float* wri = (const float*)d_in[2];
    const float* wrj = (const float*)d_in[3];
    const float* wrk = (const float*)d_in[4];
    const float* brr = (const float*)d_in[5];
    float* out = (float*)d_out;

    k_pack_x<<<(1 << 20) / 256, 256>>>(x);
    k_pack_w<<<12 * 131072 / 256, 256>>>(wrr, wri, wrj, wrk);

    cudaFuncSetAttribute(k_qdense, cudaFuncAttributeMaxDynamicSharedMemorySize, SMEM_TOTAL);
    k_qdense<<<2 * MT * NT, 256, SMEM_TOTAL>>>(brr, out);
}